// round 14
// baseline (speedup 1.0000x reference)
#include <cuda_runtime.h>
#include <cuda_fp16.h>
#include <stdint.h>

#define NE     32
#define HID    2048
#define INTER  768
#define TOPK   4
#define NT     1024
#define MAXP   (NT * TOPK)

#define KC     32
#define RSA    40                 // A smem row stride (halves)
#define RSBH   264                // B smem row stride (halves)
#define ATB    (128 * RSA * 2)    // 10240
#define BTB    (KC * RSBH * 2)    // 16896
#define STGB   (ATB + BTB)        // 27136 per stage
#define NSTG   4
#define SMMAX  (NSTG * STGB)      // 108544

#define NTHR    384               // 8 consumer warps + 4 producer warps
#define G1TILES (NE * 6 * 2)      // 384
#define G2TILES (NE * 8 * 2)      // 512
#define GU_TARGET 12

// ---------------- device scratch ----------------
__device__ int    g_counts[NE];
__device__ int    g_offsets[NE + 1];
__device__ int    g_pairTok[MAXP];
__device__ float  g_pairW[MAXP];
__device__ int    g_guDone[NE];
__device__ __half g_xh[(size_t)NT * HID];
__device__ __half g_acth[(size_t)MAXP * INTER];

// ---------------- helpers ----------------
__device__ __forceinline__ uint32_t s2u(const void* p) {
    uint32_t a;
    asm("{ .reg .u64 t; cvta.to.shared.u64 t, %1; cvt.u32.u64 %0, t; }" : "=r"(a) : "l"(p));
    return a;
}
__device__ __forceinline__ uint32_t pack2h(float a, float b) {
    __half2 h = __floats2half2_rn(a, b);
    return *(uint32_t*)&h;
}
__device__ __forceinline__ void ldsm4(uint32_t* r, uint32_t a) {
    asm volatile("ldmatrix.sync.aligned.m8n8.x4.shared.b16 {%0,%1,%2,%3}, [%4];"
                 : "=r"(r[0]), "=r"(r[1]), "=r"(r[2]), "=r"(r[3]) : "r"(a));
}
__device__ __forceinline__ void ldsm4t(uint32_t* r, uint32_t a) {
    asm volatile("ldmatrix.sync.aligned.m8n8.x4.trans.shared.b16 {%0,%1,%2,%3}, [%4];"
                 : "=r"(r[0]), "=r"(r[1]), "=r"(r[2]), "=r"(r[3]) : "r"(a));
}
#define MMA16816(c, a, b)                                                     \
    asm volatile("mma.sync.aligned.m16n8k16.row.col.f32.f16.f16.f32 "        \
                 "{%0,%1,%2,%3}, {%4,%5,%6,%7}, {%8,%9}, {%0,%1,%2,%3};"     \
                 : "+f"((c)[0]), "+f"((c)[1]), "+f"((c)[2]), "+f"((c)[3])    \
                 : "r"((a)[0]), "r"((a)[1]), "r"((a)[2]), "r"((a)[3]),       \
                   "r"((b)[0]), "r"((b)[1]))

#define BAR_SYNC(id)   asm volatile("bar.sync %0, %1;"   :: "r"(id), "n"(NTHR) : "memory")
#define BAR_ARRIVE(id) asm volatile("bar.arrive %0, %1;" :: "r"(id), "n"(NTHR) : "memory")
#define MEMBAR_CTA()   asm volatile("membar.cta;" ::: "memory")

// ---------------- routing ----------------
__global__ void k_route(const int* __restrict__ ri32, const float* __restrict__ rw) {
    __shared__ int s_cnt[NE];
    __shared__ int s_off[NE + 1];
    __shared__ int s_fill[NE];
    __shared__ int s_not64;
    int t = threadIdx.x;
    if (t < NE) { s_cnt[t] = 0; s_fill[t] = 0; g_guDone[t] = 0; }
    if (t == 0) s_not64 = 0;
    __syncthreads();
    if ((ri32[4 * t + 1] | ri32[4 * t + 3]) != 0) atomicOr(&s_not64, 1);
    __syncthreads();
    const bool is64 = (s_not64 == 0);

    int e[TOPK]; bool dup[TOPK];
#pragma unroll
    for (int j = 0; j < TOPK; j++) {
        int raw = is64 ? ri32[(t * TOPK + j) * 2] : ri32[t * TOPK + j];
        e[j] = raw & (NE - 1);
        dup[j] = false;
#pragma unroll
        for (int i = 0; i < TOPK; i++)
            if (i < j && e[i] == e[j]) dup[j] = true;
        if (!dup[j]) atomicAdd(&s_cnt[e[j]], 1);
    }
    __syncthreads();
    if (t == 0) {
        int acc = 0;
        for (int k = 0; k < NE; k++) { s_off[k] = acc; acc += s_cnt[k]; }
        s_off[NE] = acc;
    }
    __syncthreads();
    if (t < NE) { g_counts[t] = s_cnt[t]; g_offsets[t] = s_off[t]; }
    if (t == 0) g_offsets[NE] = s_off[NE];
#pragma unroll
    for (int j = 0; j < TOPK; j++) {
        if (!dup[j]) {
            int p = atomicAdd(&s_fill[e[j]], 1);
            int idx = s_off[e[j]] + p;
            g_pairTok[idx] = t;
            g_pairW[idx]   = rw[t * NE + e[j]];
        }
    }
}

// ---------------- zero output / pre-convert x ----------------
__global__ void k_zero(float4* __restrict__ out) {
    out[blockIdx.x * blockDim.x + threadIdx.x] = make_float4(0.f, 0.f, 0.f, 0.f);
}
__global__ void k_prep(const float4* __restrict__ x) {
    int i = blockIdx.x * blockDim.x + threadIdx.x;    // over NT*HID/4
    float4 v = x[i];
    ((uint2*)g_xh)[i] = make_uint2(pack2h(v.x, v.y), pack2h(v.z, v.w));
}

// ======================= warp-specialized MoE GEMM (4 producer warps) =======================
__global__ __launch_bounds__(NTHR, 1) void k_moe(const float* __restrict__ Wgu,
                                                 const float* __restrict__ Wd,
                                                 float* __restrict__ out) {
    extern __shared__ char sm[];
    __shared__ int s_tok[128];
    const int bid  = blockIdx.x;
    const int tid  = threadIdx.x;
    const int wid  = tid >> 5;      // 0..11
    const int lane = tid & 31;
    const uint32_t sb = s2u(sm);

    // consumer constants (wid < 8)
    const int wm = wid & 1;          // 64-row half
    const int wn = wid >> 1;         // 64-col slab (0..3)
    const uint32_t laneA = (uint32_t)(((lane & 15) * RSA + (lane >> 4) * 8) * 2);
    const int rr = lane & 15;
    const int hb = lane >> 4;
    const uint32_t xrL = (uint32_t)((rr & 3) << 1);
    const uint32_t bRowL = (uint32_t)(rr * (RSBH * 2));

    // producer constants (wid >= 8): 128 threads
    const int lt  = tid - 256;       // 0..127
    const int lr  = lt;              // A row
    const int br  = lt >> 2;         // B k-row 0..31
    const int bq  = lt & 3;          // B col quarter
    const uint32_t xrS = (uint32_t)((br & 3) << 1);
    const uint32_t bRowS = (uint32_t)(br * (RSBH * 2));
    const uint32_t aO = (uint32_t)(lr * 80);

    if (bid < G1TILES) {
        // ================= gate_up tile: 128 rows x 128 inter-cols (G+U) =================
        const int e   = bid / 12;
        const int sub = bid % 12;
        const int m0  = (sub / 6) * 128;
        const int n0  = (sub % 6) * 128;
        const int cnt = g_counts[e];

        if (m0 < cnt) {
            const int off = g_offsets[e];
            if (tid < 128) s_tok[tid] = (m0 + tid < cnt) ? g_pairTok[off + m0 + tid] : -1;
            __syncthreads();

            const int NCH = HID / KC;   // 64

            if (wid >= 8) {
                // -------- producer (128 threads) --------
                const int tok = s_tok[lr];
                const __half* pA = (tok >= 0) ? g_xh + (size_t)tok * HID : nullptr;
                const float* wbase = Wgu + (size_t)e * HID * (2 * INTER) + n0 + bq * 32;

                for (int it = 0; it < NCH; it++) {
                    const int s = it & 3;
                    if (it >= NSTG) BAR_SYNC(5 + s);
                    char* st = sm + s * STGB;
                    const int kk = it * KC;
                    // A copy (fp16, 16B granules, one row)
#pragma unroll
                    for (int j = 0; j < 4; j++) {
                        uint4 v = pA ? *(const uint4*)(pA + kk + j * 8) : make_uint4(0, 0, 0, 0);
                        *(uint4*)(st + aO + j * 16) = v;
                    }
                    // B: one k-row, 32 gate cols + 32 up cols
                    const float* srcg = wbase + (size_t)(kk + br) * (2 * INTER);
                    const float* srcu = srcg + INTER;
                    char* stB = st + ATB;
#pragma unroll
                    for (int j = 0; j < 4; j++) {
                        float4 f0 = *(const float4*)(srcg + j * 8);
                        float4 f1 = *(const float4*)(srcg + j * 8 + 4);
                        uint32_t ug = (uint32_t)(bq * 8 + j);
                        *(uint4*)(stB + bRowS + ((ug ^ xrS) << 4)) =
                            make_uint4(pack2h(f0.x, f0.y), pack2h(f0.z, f0.w),
                                       pack2h(f1.x, f1.y), pack2h(f1.z, f1.w));
                        float4 g0 = *(const float4*)(srcu + j * 8);
                        float4 g1 = *(const float4*)(srcu + j * 8 + 4);
                        uint32_t uu = ug + 4;
                        *(uint4*)(stB + bRowS + ((uu ^ xrS) << 4)) =
                            make_uint4(pack2h(g0.x, g0.y), pack2h(g0.z, g0.w),
                                       pack2h(g1.x, g1.y), pack2h(g1.z, g1.w));
                    }
                    MEMBAR_CTA();
                    BAR_ARRIVE(1 + s);
                }
            } else {
                // -------- consumer (256 threads) --------
                float accG[4][4][4] = {};
                float accU[4][4][4] = {};
                for (int it = 0; it < NCH; it++) {
                    const int s = it & 3;
                    BAR_SYNC(1 + s);
                    const uint32_t base = sb + s * STGB;
                    const uint32_t Ah = base, Bs = base + ATB;
#pragma unroll
                    for (int ks = 0; ks < 2; ks++) {
                        uint32_t ah[4][4];
#pragma unroll
                        for (int mt = 0; mt < 4; mt++) {
                            uint32_t ao = (uint32_t)(((wm * 64 + mt * 16) * RSA + ks * 16) * 2) + laneA;
                            ldsm4(ah[mt], Ah + ao);
                        }
#pragma unroll
                        for (int q = 0; q < 4; q++) {
                            uint32_t u0 = (uint32_t)(wn * 8 + q * 2 + hb);
                            uint32_t bo = bRowL + (uint32_t)(ks * 16 * (RSBH * 2)) + ((u0 ^ xrL) << 4);
                            uint32_t bh4[4];
                            ldsm4t(bh4, Bs + bo);
                            if (q < 2) {
#pragma unroll
                                for (int mt = 0; mt < 4; mt++) {
                                    MMA16816(accG[mt][q * 2 + 0], ah[mt], &bh4[0]);
                                    MMA16816(accG[mt][q * 2 + 1], ah[mt], &bh4[2]);
                                }
                            } else {
#pragma unroll
                                for (int mt = 0; mt < 4; mt++) {
                                    MMA16816(accU[mt][(q - 2) * 2 + 0], ah[mt], &bh4[0]);
                                    MMA16816(accU[mt][(q - 2) * 2 + 1], ah[mt], &bh4[2]);
                                }
                            }
                        }
                    }
                    BAR_ARRIVE(5 + s);
                }
                // epilogue: SwiGLU * routing weight -> g_acth (fp16)
#pragma unroll
                for (int mt = 0; mt < 4; mt++) {
                    int rl = wm * 64 + mt * 16 + (lane >> 2);
#pragma unroll
                    for (int half_ = 0; half_ < 2; half_++) {
                        int m = m0 + rl + half_ * 8;
                        if (m < cnt) {
                            int idx = off + m;
                            float w = g_pairW[idx];
                            __half* op = g_acth + (size_t)idx * INTER + n0 + wn * 32 + (lane & 3) * 2;
#pragma unroll
                            for (int nt = 0; nt < 4; nt++) {
                                float gg0 = accG[mt][nt][half_ * 2 + 0];
                                float gg1 = accG[mt][nt][half_ * 2 + 1];
                                float uu0 = accU[mt][nt][half_ * 2 + 0];
                                float uu1 = accU[mt][nt][half_ * 2 + 1];
                                float v0 = gg0 / (1.0f + __expf(-gg0)) * uu0 * w;
                                float v1 = gg1 / (1.0f + __expf(-gg1)) * uu1 * w;
                                *(uint32_t*)(op + nt * 8) = pack2h(v0, v1);
                            }
                        }
                    }
                }
            }
        }
        __threadfence();
        __syncthreads();
        if (tid == 0) atomicAdd(&g_guDone[e], 1);

    } else {
        // ================= down tile: 128 rows x 256 hid-cols, fused combine =================
        const int b2  = bid - G1TILES;
        const int e   = b2 >> 4;
        const int sub = b2 & 15;
        const int m0  = (sub >> 3) * 128;
        const int n0  = (sub & 7) * 256;
        const int cnt = g_counts[e];
        if (m0 >= cnt) return;
        const int off = g_offsets[e];

        if (tid == 0) {
            while (*(volatile int*)&g_guDone[e] < GU_TARGET) __nanosleep(128);
        }
        __syncthreads();
        __threadfence();

        __shared__ int s_row[128];
        if (tid < 128) s_row[tid] = (m0 + tid < cnt) ? off + m0 + tid : -1;
        __syncthreads();

        const int NCH = INTER / KC;   // 24

        if (wid >= 8) {
            // -------- producer (128 threads) --------
            const int pid = s_row[lr];
            const __half* pA = (pid >= 0) ? g_acth + (size_t)pid * INTER : nullptr;
            const float* wbase = Wd + (size_t)e * INTER * HID + n0 + bq * 64;

            for (int it = 0; it < NCH; it++) {
                const int s = it & 3;
                if (it >= NSTG) BAR_SYNC(5 + s);
                char* st = sm + s * STGB;
                const int kk = it * KC;
#pragma unroll
                for (int j = 0; j < 4; j++) {
                    uint4 v = pA ? *(const uint4*)(pA + kk + j * 8) : make_uint4(0, 0, 0, 0);
                    *(uint4*)(st + aO + j * 16) = v;
                }
                const float* src = wbase + (size_t)(kk + br) * HID;
                char* stB = st + ATB;
#pragma unroll
                for (int j = 0; j < 8; j++) {
                    float4 f0 = *(const float4*)(src + j * 8);
                    float4 f1 = *(const float4*)(src + j * 8 + 4);
                    uint32_t u = (uint32_t)(bq * 8 + j);
                    *(uint4*)(stB + bRowS + ((u ^ xrS) << 4)) =
                        make_uint4(pack2h(f0.x, f0.y), pack2h(f0.z, f0.w),
                                   pack2h(f1.x, f1.y), pack2h(f1.z, f1.w));
                }
                MEMBAR_CTA();
                BAR_ARRIVE(1 + s);
            }
        } else {
            // -------- consumer (256 threads) --------
            float acc[4][8][4] = {};
            for (int it = 0; it < NCH; it++) {
                const int s = it & 3;
                BAR_SYNC(1 + s);
                const uint32_t base = sb + s * STGB;
                const uint32_t Ah = base, Bs = base + ATB;
#pragma unroll
                for (int ks = 0; ks < 2; ks++) {
                    uint32_t ah[4][4];
#pragma unroll
                    for (int mt = 0; mt < 4; mt++) {
                        uint32_t ao = (uint32_t)(((wm * 64 + mt * 16) * RSA + ks * 16) * 2) + laneA;
                        ldsm4(ah[mt], Ah + ao);
                    }
#pragma unroll
                    for (int q = 0; q < 4; q++) {
                        uint32_t u0 = (uint32_t)(wn * 8 + q * 2 + hb);
                        uint32_t bo = bRowL + (uint32_t)(ks * 16 * (RSBH * 2)) + ((u0 ^ xrL) << 4);
                        uint32_t bh4[4];
                        ldsm4t(bh4, Bs + bo);
#pragma unroll
                        for (int mt = 0; mt < 4; mt++) {
                            MMA16816(acc[mt][q * 2 + 0], ah[mt], &bh4[0]);
                            MMA16816(acc[mt][q * 2 + 1], ah[mt], &bh4[2]);
                        }
                    }
                }
                BAR_ARRIVE(5 + s);
            }
            // fused combine: atomic accumulate into out
#pragma unroll
            for (int mt = 0; mt < 4; mt++) {
                int rl = wm * 64 + mt * 16 + (lane >> 2);
#pragma unroll
                for (int half_ = 0; half_ < 2; half_++) {
                    int m = m0 + rl + half_ * 8;
                    if (m < cnt) {
                        int tok = g_pairTok[off + m];
                        float* op = out + (size_t)tok * HID + n0 + wn * 64 + (lane & 3) * 2;
#pragma unroll
                        for (int nt = 0; nt < 8; nt++) {
                            atomicAdd(op + nt * 8 + 0, acc[mt][nt][half_ * 2 + 0]);
                            atomicAdd(op + nt * 8 + 1, acc[mt][nt][half_ * 2 + 1]);
                        }
                    }
                }
            }
        }
    }
}

// ---------------- launch ----------------
extern "C" void kernel_launch(void* const* d_in, const int* in_sizes, int n_in,
                              void* d_out, int out_size) {
    const float* x   = nullptr;
    const float* rw  = nullptr;
    const float* Wgu = nullptr;
    const float* Wd  = nullptr;
    const int*   ri  = nullptr;
    for (int i = 0; i < n_in; i++) {
        switch (in_sizes[i]) {
            case 2097152:   x   = (const float*)d_in[i]; break;
            case 32768:     rw  = (const float*)d_in[i]; break;
            case 100663296: Wgu = (const float*)d_in[i]; break;
            case 50331648:  Wd  = (const float*)d_in[i]; break;
            case 4096:      ri  = (const int*)d_in[i];   break;
            default: break;
        }
    }
    float* out = (float*)d_out;

    cudaFuncSetAttribute(k_moe, cudaFuncAttributeMaxDynamicSharedMemorySize, SMMAX);

    k_route<<<1, NT>>>(ri, rw);
    k_zero<<<(NT * HID / 4) / 256, 256>>>((float4*)out);
    k_prep<<<(NT * HID / 4) / 256, 256>>>((const float4*)x);  // 3rd launch: ncu captures k_moe
    k_moe<<<G1TILES + G2TILES, NTHR, SMMAX>>>(Wgu, Wd, out);
}

// round 15
// speedup vs baseline: 1.1882x; 1.1882x over previous
#include <cuda_runtime.h>
#include <cuda_fp16.h>
#include <stdint.h>

#define NE     32
#define HID    2048
#define INTER  768
#define TOPK   4
#define NT     1024
#define MAXP   (NT * TOPK)

#define KC     32
#define RSA    40                 // A smem row stride (halves)
#define RSB    136                // B smem row stride (halves): 128 cols + 8 pad
#define ATB    (128 * RSA * 2)    // 10240
#define BTB    (KC * RSB * 2)     // 8704
#define STGB   (ATB + BTB)        // 18944
#define SMMAX  (2 * STGB)         // 37888

#define G1TILES (NE * 12 * 2)     // 768: expert x 12 n-tiles(64 inter) x 2 m
#define G2TILES (NE * 16 * 2)     // 1024: expert x 16 n-tiles(128 hid) x 2 m
#define GU_TARGET 24

// ---------------- device scratch ----------------
__device__ int    g_counts[NE];
__device__ int    g_offsets[NE + 1];
__device__ int    g_pairTok[MAXP];
__device__ float  g_pairW[MAXP];
__device__ int    g_guDone[NE];
__device__ __half g_xh[(size_t)NT * HID];
__device__ __half g_acth[(size_t)MAXP * INTER];

// ---------------- helpers ----------------
__device__ __forceinline__ uint32_t s2u(const void* p) {
    uint32_t a;
    asm("{ .reg .u64 t; cvta.to.shared.u64 t, %1; cvt.u32.u64 %0, t; }" : "=r"(a) : "l"(p));
    return a;
}
__device__ __forceinline__ uint32_t pack2h(float a, float b) {
    __half2 h = __floats2half2_rn(a, b);
    return *(uint32_t*)&h;
}
__device__ __forceinline__ void ldsm4(uint32_t* r, uint32_t a) {
    asm volatile("ldmatrix.sync.aligned.m8n8.x4.shared.b16 {%0,%1,%2,%3}, [%4];"
                 : "=r"(r[0]), "=r"(r[1]), "=r"(r[2]), "=r"(r[3]) : "r"(a));
}
__device__ __forceinline__ void ldsm4t(uint32_t* r, uint32_t a) {
    asm volatile("ldmatrix.sync.aligned.m8n8.x4.trans.shared.b16 {%0,%1,%2,%3}, [%4];"
                 : "=r"(r[0]), "=r"(r[1]), "=r"(r[2]), "=r"(r[3]) : "r"(a));
}
#define MMA16816(c, a, b)                                                     \
    asm volatile("mma.sync.aligned.m16n8k16.row.col.f32.f16.f16.f32 "        \
                 "{%0,%1,%2,%3}, {%4,%5,%6,%7}, {%8,%9}, {%0,%1,%2,%3};"     \
                 : "+f"((c)[0]), "+f"((c)[1]), "+f"((c)[2]), "+f"((c)[3])    \
                 : "r"((a)[0]), "r"((a)[1]), "r"((a)[2]), "r"((a)[3]),       \
                   "r"((b)[0]), "r"((b)[1]))

// ---------------- routing ----------------
__global__ void k_route(const int* __restrict__ ri32, const float* __restrict__ rw) {
    __shared__ int s_cnt[NE];
    __shared__ int s_off[NE + 1];
    __shared__ int s_fill[NE];
    __shared__ int s_not64;
    int t = threadIdx.x;
    if (t < NE) { s_cnt[t] = 0; s_fill[t] = 0; g_guDone[t] = 0; }
    if (t == 0) s_not64 = 0;
    __syncthreads();
    if ((ri32[4 * t + 1] | ri32[4 * t + 3]) != 0) atomicOr(&s_not64, 1);
    __syncthreads();
    const bool is64 = (s_not64 == 0);

    int e[TOPK]; bool dup[TOPK];
#pragma unroll
    for (int j = 0; j < TOPK; j++) {
        int raw = is64 ? ri32[(t * TOPK + j) * 2] : ri32[t * TOPK + j];
        e[j] = raw & (NE - 1);
        dup[j] = false;
#pragma unroll
        for (int i = 0; i < TOPK; i++)
            if (i < j && e[i] == e[j]) dup[j] = true;
        if (!dup[j]) atomicAdd(&s_cnt[e[j]], 1);
    }
    __syncthreads();
    if (t == 0) {
        int acc = 0;
        for (int k = 0; k < NE; k++) { s_off[k] = acc; acc += s_cnt[k]; }
        s_off[NE] = acc;
    }
    __syncthreads();
    if (t < NE) { g_counts[t] = s_cnt[t]; g_offsets[t] = s_off[t]; }
    if (t == 0) g_offsets[NE] = s_off[NE];
#pragma unroll
    for (int j = 0; j < TOPK; j++) {
        if (!dup[j]) {
            int p = atomicAdd(&s_fill[e[j]], 1);
            int idx = s_off[e[j]] + p;
            g_pairTok[idx] = t;
            g_pairW[idx]   = rw[t * NE + e[j]];
        }
    }
}

// ---------------- zero output / pre-convert x ----------------
__global__ void k_zero(float4* __restrict__ out) {
    out[blockIdx.x * blockDim.x + threadIdx.x] = make_float4(0.f, 0.f, 0.f, 0.f);
}
__global__ void k_prep(const float4* __restrict__ x) {
    int i = blockIdx.x * blockDim.x + threadIdx.x;    // over NT*HID/4
    float4 v = x[i];
    ((uint2*)g_xh)[i] = make_uint2(pack2h(v.x, v.y), pack2h(v.z, v.w));
}

// ======================= MoE GEMM: 128 threads, 4 warps of 64x64, 2 CTAs/SM =======================
__global__ __launch_bounds__(128, 2) void k_moe(const float* __restrict__ Wgu,
                                                const float* __restrict__ Wd,
                                                float* __restrict__ out) {
    extern __shared__ char sm[];
    __shared__ int s_tok[128];
    const int bid  = blockIdx.x;
    const int tid  = threadIdx.x;
    const int wid  = tid >> 5;      // 0..3
    const int lane = tid & 31;
    const int wm   = wid & 1;       // 64-row half
    const int wn   = wid >> 1;      // 64-col slab (0..1)
    const uint32_t sb = s2u(sm);

    // ldsm lane constants
    const uint32_t laneA = (uint32_t)(((lane & 15) * RSA + (lane >> 4) * 8) * 2);
    const uint32_t laneB = (uint32_t)(((lane & 15) * RSB + (lane >> 4) * 8) * 2);

    // loader constants
    const int arow = tid;            // A row 0..127 (one row per thread)
    const int br   = tid >> 2;       // B k-row 0..31
    const int bq   = tid & 3;        // B col quarter (32 cols)
    const uint32_t aO = (uint32_t)(arow * 80);
    const uint32_t bO = (uint32_t)(br * (RSB * 2) + bq * 64);

    if (bid < G1TILES) {
        // ====== gate_up tile: 128 rows x 64 inter-cols (B = [G0-31|U0-31|G32-63|U32-63]) ======
        const int e   = bid / 24;
        const int sub = bid % 24;
        const int m0  = (sub / 12) * 128;
        const int n0  = (sub % 12) * 64;
        const int cnt = g_counts[e];

        if (m0 < cnt) {
            const int off = g_offsets[e];
            s_tok[tid] = (m0 + tid < cnt) ? g_pairTok[off + m0 + tid] : -1;
            __syncthreads();

            const int atok = s_tok[arow];
            const __half* aP = (atok >= 0) ? g_xh + (size_t)atok * HID : nullptr;
            // this thread's B source: 32 cols, gate or up
            const float* bP = Wgu + (size_t)e * HID * (2 * INTER) + n0
                              + (bq >> 1) * 32 + (bq & 1) * INTER;

            float accG[4][4][4] = {};
            float accU[4][4][4] = {};

            const int NCH = HID / KC;   // 64
            for (int it = 0; it <= NCH; it++) {
                uint4 a4[4];
                float4 bf[8];
                if (it < NCH) {
                    const int kk = it * KC;
#pragma unroll
                    for (int j = 0; j < 4; j++)
                        a4[j] = aP ? *(const uint4*)(aP + kk + j * 8) : make_uint4(0, 0, 0, 0);
                    const float* src = bP + (size_t)(kk + br) * (2 * INTER);
#pragma unroll
                    for (int j = 0; j < 8; j++)
                        bf[j] = *(const float4*)(src + j * 4);
                }
                if (it > 0) {
                    const uint32_t base = sb + ((it - 1) & 1) * STGB;
                    const uint32_t Ah = base, Bs = base + ATB;
#pragma unroll
                    for (int ks = 0; ks < 2; ks++) {
                        uint32_t ah[4][4];
#pragma unroll
                        for (int mt = 0; mt < 4; mt++) {
                            uint32_t ao = (uint32_t)(((wm * 64 + mt * 16) * RSA + ks * 16) * 2) + laneA;
                            ldsm4(ah[mt], Ah + ao);
                        }
#pragma unroll
                        for (int q = 0; q < 4; q++) {
                            uint32_t bo = (uint32_t)((ks * 16 * RSB + wn * 64 + q * 16) * 2) + laneB;
                            uint32_t bh4[4];
                            ldsm4t(bh4, Bs + bo);
                            if (q < 2) {
#pragma unroll
                                for (int mt = 0; mt < 4; mt++) {
                                    MMA16816(accG[mt][q * 2 + 0], ah[mt], &bh4[0]);
                                    MMA16816(accG[mt][q * 2 + 1], ah[mt], &bh4[2]);
                                }
                            } else {
#pragma unroll
                                for (int mt = 0; mt < 4; mt++) {
                                    MMA16816(accU[mt][(q - 2) * 2 + 0], ah[mt], &bh4[0]);
                                    MMA16816(accU[mt][(q - 2) * 2 + 1], ah[mt], &bh4[2]);
                                }
                            }
                        }
                    }
                }
                if (it < NCH) {
                    char* st = sm + (it & 1) * STGB;
#pragma unroll
                    for (int j = 0; j < 4; j++)
                        *(uint4*)(st + aO + j * 16) = a4[j];
                    char* stB = st + ATB;
#pragma unroll
                    for (int j = 0; j < 4; j++) {
                        *(uint4*)(stB + bO + j * 16) =
                            make_uint4(pack2h(bf[2 * j].x, bf[2 * j].y),
                                       pack2h(bf[2 * j].z, bf[2 * j].w),
                                       pack2h(bf[2 * j + 1].x, bf[2 * j + 1].y),
                                       pack2h(bf[2 * j + 1].z, bf[2 * j + 1].w));
                    }
                }
                __syncthreads();
            }

            // epilogue: SwiGLU * routing weight -> g_acth (fp16)
#pragma unroll
            for (int mt = 0; mt < 4; mt++) {
                int rl = wm * 64 + mt * 16 + (lane >> 2);
#pragma unroll
                for (int half_ = 0; half_ < 2; half_++) {
                    int m = m0 + rl + half_ * 8;
                    if (m < cnt) {
                        int idx = off + m;
                        float w = g_pairW[idx];
                        __half* op = g_acth + (size_t)idx * INTER + n0 + wn * 32 + (lane & 3) * 2;
#pragma unroll
                        for (int nt = 0; nt < 4; nt++) {
                            float gg0 = accG[mt][nt][half_ * 2 + 0];
                            float gg1 = accG[mt][nt][half_ * 2 + 1];
                            float uu0 = accU[mt][nt][half_ * 2 + 0];
                            float uu1 = accU[mt][nt][half_ * 2 + 1];
                            float v0 = gg0 / (1.0f + __expf(-gg0)) * uu0 * w;
                            float v1 = gg1 / (1.0f + __expf(-gg1)) * uu1 * w;
                            *(uint32_t*)(op + nt * 8) = pack2h(v0, v1);
                        }
                    }
                }
            }
        }
        __threadfence();
        __syncthreads();
        if (tid == 0) atomicAdd(&g_guDone[e], 1);

    } else {
        // ====== down tile: 128 rows x 128 hid-cols, fused combine ======
        const int b2  = bid - G1TILES;
        const int e   = b2 >> 5;
        const int sub = b2 & 31;
        const int m0  = (sub >> 4) * 128;
        const int n0  = (sub & 15) * 128;
        const int cnt = g_counts[e];
        if (m0 >= cnt) return;
        const int off = g_offsets[e];

        if (tid == 0) {
            while (*(volatile int*)&g_guDone[e] < GU_TARGET) __nanosleep(128);
        }
        __syncthreads();
        __threadfence();

        __shared__ int s_row[128];
        s_row[tid] = (m0 + tid < cnt) ? off + m0 + tid : -1;
        __syncthreads();

        const int apid = s_row[arow];
        const __half* aP = (apid >= 0) ? g_acth + (size_t)apid * INTER : nullptr;
        const float* bP = Wd + (size_t)e * INTER * HID + n0 + bq * 32;

        float acc[4][8][4] = {};

        const int NCH = INTER / KC;   // 24
        for (int it = 0; it <= NCH; it++) {
            uint4 a4[4];
            float4 bf[8];
            if (it < NCH) {
                const int kk = it * KC;
#pragma unroll
                for (int j = 0; j < 4; j++)
                    a4[j] = aP ? *(const uint4*)(aP + kk + j * 8) : make_uint4(0, 0, 0, 0);
                const float* src = bP + (size_t)(kk + br) * HID;
#pragma unroll
                for (int j = 0; j < 8; j++)
                    bf[j] = *(const float4*)(src + j * 4);
            }
            if (it > 0) {
                const uint32_t base = sb + ((it - 1) & 1) * STGB;
                const uint32_t Ah = base, Bs = base + ATB;
#pragma unroll
                for (int ks = 0; ks < 2; ks++) {
                    uint32_t ah[4][4];
#pragma unroll
                    for (int mt = 0; mt < 4; mt++) {
                        uint32_t ao = (uint32_t)(((wm * 64 + mt * 16) * RSA + ks * 16) * 2) + laneA;
                        ldsm4(ah[mt], Ah + ao);
                    }
#pragma unroll
                    for (int q = 0; q < 4; q++) {
                        uint32_t bo = (uint32_t)((ks * 16 * RSB + wn * 64 + q * 16) * 2) + laneB;
                        uint32_t bh4[4];
                        ldsm4t(bh4, Bs + bo);
#pragma unroll
                        for (int mt = 0; mt < 4; mt++) {
                            MMA16816(acc[mt][q * 2 + 0], ah[mt], &bh4[0]);
                            MMA16816(acc[mt][q * 2 + 1], ah[mt], &bh4[2]);
                        }
                    }
                }
            }
            if (it < NCH) {
                char* st = sm + (it & 1) * STGB;
#pragma unroll
                for (int j = 0; j < 4; j++)
                    *(uint4*)(st + aO + j * 16) = a4[j];
                char* stB = st + ATB;
#pragma unroll
                for (int j = 0; j < 4; j++) {
                    *(uint4*)(stB + bO + j * 16) =
                        make_uint4(pack2h(bf[2 * j].x, bf[2 * j].y),
                                   pack2h(bf[2 * j].z, bf[2 * j].w),
                                   pack2h(bf[2 * j + 1].x, bf[2 * j + 1].y),
                                   pack2h(bf[2 * j + 1].z, bf[2 * j + 1].w));
                }
            }
            __syncthreads();
        }

        // fused combine: atomic accumulate into out
#pragma unroll
        for (int mt = 0; mt < 4; mt++) {
            int rl = wm * 64 + mt * 16 + (lane >> 2);
#pragma unroll
            for (int half_ = 0; half_ < 2; half_++) {
                int m = m0 + rl + half_ * 8;
                if (m < cnt) {
                    int tok = g_pairTok[off + m];
                    float* op = out + (size_t)tok * HID + n0 + wn * 64 + (lane & 3) * 2;
#pragma unroll
                    for (int nt = 0; nt < 8; nt++) {
                        atomicAdd(op + nt * 8 + 0, acc[mt][nt][half_ * 2 + 0]);
                        atomicAdd(op + nt * 8 + 1, acc[mt][nt][half_ * 2 + 1]);
                    }
                }
            }
        }
    }
}

// ---------------- launch ----------------
extern "C" void kernel_launch(void* const* d_in, const int* in_sizes, int n_in,
                              void* d_out, int out_size) {
    const float* x   = nullptr;
    const float* rw  = nullptr;
    const float* Wgu = nullptr;
    const float* Wd  = nullptr;
    const int*   ri  = nullptr;
    for (int i = 0; i < n_in; i++) {
        switch (in_sizes[i]) {
            case 2097152:   x   = (const float*)d_in[i]; break;
            case 32768:     rw  = (const float*)d_in[i]; break;
            case 100663296: Wgu = (const float*)d_in[i]; break;
            case 50331648:  Wd  = (const float*)d_in[i]; break;
            case 4096:      ri  = (const int*)d_in[i];   break;
            default: break;
        }
    }
    float* out = (float*)d_out;

    cudaFuncSetAttribute(k_moe, cudaFuncAttributeMaxDynamicSharedMemorySize, SMMAX);

    k_route<<<1, NT>>>(ri, rw);
    k_zero<<<(NT * HID / 4) / 256, 256>>>((float4*)out);
    k_prep<<<(NT * HID / 4) / 256, 256>>>((const float4*)x);  // 3rd launch: ncu captures k_moe
    k_moe<<<G1TILES + G2TILES, 128, SMMAX>>>(Wgu, Wd, out);
}

// round 16
// speedup vs baseline: 1.9472x; 1.6388x over previous
#include <cuda_runtime.h>
#include <cuda_fp16.h>
#include <stdint.h>

#define NE     32
#define HID    2048
#define INTER  768
#define TOPK   4
#define NT     1024
#define MAXP   (NT * TOPK)

#define KC     32
#define RSA    40                 // A smem row stride (halves)
#define RSBH   264                // B smem row stride (halves)
#define ATB    (128 * RSA * 2)    // 10240
#define BTB    (KC * RSBH * 2)    // 16896
#define STGB   (ATB + BTB)        // 27136 per stage
#define SMMAX  (2 * STGB)         // 54272

#define G1TILES (NE * 6 * 2)      // 384
#define G2TILES (NE * 8 * 2)      // 512
#define GU_TARGET 12

// ---------------- device scratch ----------------
__device__ int    g_counts[NE];
__device__ int    g_offsets[NE + 1];
__device__ int    g_pairTok[MAXP];
__device__ float  g_pairW[MAXP];
__device__ int    g_guDone[NE];
__device__ __half g_xh[(size_t)NT * HID];
__device__ __half g_acth[(size_t)MAXP * INTER];

// ---------------- helpers ----------------
__device__ __forceinline__ uint32_t s2u(const void* p) {
    uint32_t a;
    asm("{ .reg .u64 t; cvta.to.shared.u64 t, %1; cvt.u32.u64 %0, t; }" : "=r"(a) : "l"(p));
    return a;
}
__device__ __forceinline__ uint32_t pack2h(float a, float b) {
    __half2 h = __floats2half2_rn(a, b);
    return *(uint32_t*)&h;
}
__device__ __forceinline__ void ldsm4(uint32_t* r, uint32_t a) {
    asm volatile("ldmatrix.sync.aligned.m8n8.x4.shared.b16 {%0,%1,%2,%3}, [%4];"
                 : "=r"(r[0]), "=r"(r[1]), "=r"(r[2]), "=r"(r[3]) : "r"(a));
}
__device__ __forceinline__ void ldsm4t(uint32_t* r, uint32_t a) {
    asm volatile("ldmatrix.sync.aligned.m8n8.x4.trans.shared.b16 {%0,%1,%2,%3}, [%4];"
                 : "=r"(r[0]), "=r"(r[1]), "=r"(r[2]), "=r"(r[3]) : "r"(a));
}
#define MMA16816(c, a, b)                                                     \
    asm volatile("mma.sync.aligned.m16n8k16.row.col.f32.f16.f16.f32 "        \
                 "{%0,%1,%2,%3}, {%4,%5,%6,%7}, {%8,%9}, {%0,%1,%2,%3};"     \
                 : "+f"((c)[0]), "+f"((c)[1]), "+f"((c)[2]), "+f"((c)[3])    \
                 : "r"((a)[0]), "r"((a)[1]), "r"((a)[2]), "r"((a)[3]),       \
                   "r"((b)[0]), "r"((b)[1]))

// ---------------- routing ----------------
__global__ void k_route(const int* __restrict__ ri32, const float* __restrict__ rw) {
    __shared__ int s_cnt[NE];
    __shared__ int s_off[NE + 1];
    __shared__ int s_fill[NE];
    __shared__ int s_not64;
    int t = threadIdx.x;
    if (t < NE) { s_cnt[t] = 0; s_fill[t] = 0; g_guDone[t] = 0; }
    if (t == 0) s_not64 = 0;
    __syncthreads();
    if ((ri32[4 * t + 1] | ri32[4 * t + 3]) != 0) atomicOr(&s_not64, 1);
    __syncthreads();
    const bool is64 = (s_not64 == 0);

    int e[TOPK]; bool dup[TOPK];
#pragma unroll
    for (int j = 0; j < TOPK; j++) {
        int raw = is64 ? ri32[(t * TOPK + j) * 2] : ri32[t * TOPK + j];
        e[j] = raw & (NE - 1);
        dup[j] = false;
#pragma unroll
        for (int i = 0; i < TOPK; i++)
            if (i < j && e[i] == e[j]) dup[j] = true;
        if (!dup[j]) atomicAdd(&s_cnt[e[j]], 1);
    }
    __syncthreads();
    if (t == 0) {
        int acc = 0;
        for (int k = 0; k < NE; k++) { s_off[k] = acc; acc += s_cnt[k]; }
        s_off[NE] = acc;
    }
    __syncthreads();
    if (t < NE) { g_counts[t] = s_cnt[t]; g_offsets[t] = s_off[t]; }
    if (t == 0) g_offsets[NE] = s_off[NE];
#pragma unroll
    for (int j = 0; j < TOPK; j++) {
        if (!dup[j]) {
            int p = atomicAdd(&s_fill[e[j]], 1);
            int idx = s_off[e[j]] + p;
            g_pairTok[idx] = t;
            g_pairW[idx]   = rw[t * NE + e[j]];
        }
    }
}

// ---------------- zero output / pre-convert x ----------------
__global__ void k_zero(float4* __restrict__ out) {
    out[blockIdx.x * blockDim.x + threadIdx.x] = make_float4(0.f, 0.f, 0.f, 0.f);
}
__global__ void k_prep(const float4* __restrict__ x) {
    int i = blockIdx.x * blockDim.x + threadIdx.x;    // over NT*HID/4
    float4 v = x[i];
    ((uint2*)g_xh)[i] = make_uint2(pack2h(v.x, v.y), pack2h(v.z, v.w));
}

// ======================= merged GEMM kernel (fp16, 64x64 warp tiles, fp16 A path) =======================
__global__ __launch_bounds__(256, 1) void k_moe(const float* __restrict__ Wgu,
                                                const float* __restrict__ Wd,
                                                float* __restrict__ out) {
    extern __shared__ char sm[];
    __shared__ int s_tok[128];
    const int bid  = blockIdx.x;
    const int tid  = threadIdx.x;
    const int wid  = tid >> 5;
    const int lane = tid & 31;
    const int wm   = wid & 1;       // 64-row half
    const int wn   = wid >> 1;      // 64-col slab (0..3)
    const uint32_t sb = s2u(sm);

    // ldsm lane constants
    const uint32_t laneA = (uint32_t)(((lane & 15) * RSA + (lane >> 4) * 8) * 2);
    const int rr = lane & 15;
    const int hb = lane >> 4;
    const uint32_t xrL = (uint32_t)((rr & 3) << 1);
    const uint32_t bRowL = (uint32_t)(rr * (RSBH * 2));

    // loader constants (A now fp16: 16 halves = 32B = 2 uint4 per thread)
    const int arow = tid >> 1;              // A row 0..127
    const int ak0  = (tid & 1) * 16;        // A k offset (halves)
    const int brow = tid >> 3;              // B k-row 0..31
    const int bc8  = tid & 7;               // B col group
    const uint32_t xrS = (uint32_t)((brow & 3) << 1);
    const uint32_t bRowS = (uint32_t)(brow * (RSBH * 2));
    const uint32_t aO = (uint32_t)((arow * RSA + ak0) * 2);

    if (bid < G1TILES) {
        // ================= gate_up tile: 128 rows x 128 inter-cols (G+U) =================
        const int e   = bid / 12;
        const int sub = bid % 12;
        const int m0  = (sub / 6) * 128;
        const int n0  = (sub % 6) * 128;
        const int cnt = g_counts[e];

        if (m0 < cnt) {
            const int off = g_offsets[e];
            if (tid < 128) s_tok[tid] = (m0 + tid < cnt) ? g_pairTok[off + m0 + tid] : -1;
            __syncthreads();

            const float* WgP = Wgu + (size_t)e * HID * (2 * INTER) + n0;
            const int atok = s_tok[arow];
            const __half* aP = (atok >= 0) ? g_xh + (size_t)atok * HID + ak0 : nullptr;

            float accG[4][4][4] = {};
            float accU[4][4][4] = {};

            const int NCH = HID / KC;   // 64
            for (int it = 0; it <= NCH; it++) {
                uint4 a0, a1;
                float4 gq[4], uq[4];
                if (it < NCH) {
                    const int kk = it * KC;
                    if (aP) {
                        a0 = *(const uint4*)(aP + kk);
                        a1 = *(const uint4*)(aP + kk + 8);
                    } else {
                        a0 = make_uint4(0, 0, 0, 0);
                        a1 = make_uint4(0, 0, 0, 0);
                    }
                    const float* bbase = WgP + (size_t)(kk + brow) * (2 * INTER);
#pragma unroll
                    for (int q = 0; q < 4; q++) {
                        gq[q] = *(const float4*)(bbase + (q * 8 + bc8) * 4);
                        uq[q] = *(const float4*)(bbase + INTER + (q * 8 + bc8) * 4);
                    }
                }
                if (it > 0) {
                    const uint32_t base = sb + ((it - 1) & 1) * STGB;
                    const uint32_t Ah = base, Bs = base + ATB;
#pragma unroll
                    for (int ks = 0; ks < 2; ks++) {
                        uint32_t ah[4][4];
#pragma unroll
                        for (int mt = 0; mt < 4; mt++) {
                            uint32_t ao = (uint32_t)(((wm * 64 + mt * 16) * RSA + ks * 16) * 2) + laneA;
                            ldsm4(ah[mt], Ah + ao);
                        }
#pragma unroll
                        for (int q = 0; q < 4; q++) {
                            uint32_t u0 = (uint32_t)(wn * 8 + q * 2 + hb);
                            uint32_t bo = bRowL + (uint32_t)(ks * 16 * (RSBH * 2)) + ((u0 ^ xrL) << 4);
                            uint32_t bh4[4];
                            ldsm4t(bh4, Bs + bo);
                            if (q < 2) {
#pragma unroll
                                for (int mt = 0; mt < 4; mt++) {
                                    MMA16816(accG[mt][q * 2 + 0], ah[mt], &bh4[0]);
                                    MMA16816(accG[mt][q * 2 + 1], ah[mt], &bh4[2]);
                                }
                            } else {
#pragma unroll
                                for (int mt = 0; mt < 4; mt++) {
                                    MMA16816(accU[mt][(q - 2) * 2 + 0], ah[mt], &bh4[0]);
                                    MMA16816(accU[mt][(q - 2) * 2 + 1], ah[mt], &bh4[2]);
                                }
                            }
                        }
                    }
                }
                if (it < NCH) {
                    char* st = sm + (it & 1) * STGB;
                    *(uint4*)(st + aO)      = a0;
                    *(uint4*)(st + aO + 16) = a1;
                    char* stB = st + ATB;
#pragma unroll
                    for (int q = 0; q < 4; q++) {
                        uint32_t ug = (uint32_t)(q * 8 + (bc8 >> 1));
                        uint32_t byg = bRowS + ((ug ^ xrS) << 4) + (uint32_t)((bc8 & 1) * 8);
                        *(uint2*)(stB + byg) = make_uint2(pack2h(gq[q].x, gq[q].y),
                                                          pack2h(gq[q].z, gq[q].w));
                        uint32_t uu = ug + 4;
                        uint32_t byu = bRowS + ((uu ^ xrS) << 4) + (uint32_t)((bc8 & 1) * 8);
                        *(uint2*)(stB + byu) = make_uint2(pack2h(uq[q].x, uq[q].y),
                                                          pack2h(uq[q].z, uq[q].w));
                    }
                }
                __syncthreads();
            }

            // epilogue: SwiGLU * routing weight -> g_acth (fp16)
#pragma unroll
            for (int mt = 0; mt < 4; mt++) {
                int rl = wm * 64 + mt * 16 + (lane >> 2);
#pragma unroll
                for (int half_ = 0; half_ < 2; half_++) {
                    int m = m0 + rl + half_ * 8;
                    if (m < cnt) {
                        int idx = off + m;
                        float w = g_pairW[idx];
                        __half* op = g_acth + (size_t)idx * INTER + n0 + wn * 32 + (lane & 3) * 2;
#pragma unroll
                        for (int nt = 0; nt < 4; nt++) {
                            float gg0 = accG[mt][nt][half_ * 2 + 0];
                            float gg1 = accG[mt][nt][half_ * 2 + 1];
                            float uu0 = accU[mt][nt][half_ * 2 + 0];
                            float uu1 = accU[mt][nt][half_ * 2 + 1];
                            float v0 = gg0 / (1.0f + __expf(-gg0)) * uu0 * w;
                            float v1 = gg1 / (1.0f + __expf(-gg1)) * uu1 * w;
                            *(uint32_t*)(op + nt * 8) = pack2h(v0, v1);
                        }
                    }
                }
            }
        }
        __threadfence();
        __syncthreads();
        if (tid == 0) atomicAdd(&g_guDone[e], 1);

    } else {
        // ================= down tile: 128 rows x 256 hid-cols, fused combine =================
        const int b2  = bid - G1TILES;
        const int e   = b2 >> 4;
        const int sub = b2 & 15;
        const int m0  = (sub >> 3) * 128;
        const int n0  = (sub & 7) * 256;
        const int cnt = g_counts[e];
        if (m0 >= cnt) return;
        const int off = g_offsets[e];

        if (tid == 0) {
            while (*(volatile int*)&g_guDone[e] < GU_TARGET) __nanosleep(128);
        }
        __syncthreads();
        __threadfence();

        __shared__ int s_row[128];
        if (tid < 128) s_row[tid] = (m0 + tid < cnt) ? off + m0 + tid : -1;
        __syncthreads();

        const float* WdP = Wd + (size_t)e * INTER * HID + n0;
        const int apid = s_row[arow];
        const __half* aP = (apid >= 0) ? g_acth + (size_t)apid * INTER + ak0 : nullptr;

        float acc[4][8][4] = {};

        const int NCH = INTER / KC;   // 24
        for (int it = 0; it <= NCH; it++) {
            uint4 a0, a1;
            float4 bq[8];
            if (it < NCH) {
                const int kk = it * KC;
                if (aP) {
                    a0 = *(const uint4*)(aP + kk);
                    a1 = *(const uint4*)(aP + kk + 8);
                } else {
                    a0 = make_uint4(0, 0, 0, 0);
                    a1 = make_uint4(0, 0, 0, 0);
                }
                const float* bbase = WdP + (size_t)(kk + brow) * HID;
#pragma unroll
                for (int q = 0; q < 8; q++)
                    bq[q] = *(const float4*)(bbase + (q * 8 + bc8) * 4);
            }
            if (it > 0) {
                const uint32_t base = sb + ((it - 1) & 1) * STGB;
                const uint32_t Ah = base, Bs = base + ATB;
#pragma unroll
                for (int ks = 0; ks < 2; ks++) {
                    uint32_t ah[4][4];
#pragma unroll
                    for (int mt = 0; mt < 4; mt++) {
                        uint32_t ao = (uint32_t)(((wm * 64 + mt * 16) * RSA + ks * 16) * 2) + laneA;
                        ldsm4(ah[mt], Ah + ao);
                    }
#pragma unroll
                    for (int q = 0; q < 4; q++) {
                        uint32_t u0 = (uint32_t)(wn * 8 + q * 2 + hb);
                        uint32_t bo = bRowL + (uint32_t)(ks * 16 * (RSBH * 2)) + ((u0 ^ xrL) << 4);
                        uint32_t bh4[4];
                        ldsm4t(bh4, Bs + bo);
#pragma unroll
                        for (int mt = 0; mt < 4; mt++) {
                            MMA16816(acc[mt][q * 2 + 0], ah[mt], &bh4[0]);
                            MMA16816(acc[mt][q * 2 + 1], ah[mt], &bh4[2]);
                        }
                    }
                }
            }
            if (it < NCH) {
                char* st = sm + (it & 1) * STGB;
                *(uint4*)(st + aO)      = a0;
                *(uint4*)(st + aO + 16) = a1;
                char* stB = st + ATB;
#pragma unroll
                for (int q = 0; q < 8; q++) {
                    uint32_t u = (uint32_t)(q * 4 + (bc8 >> 1));
                    uint32_t by = bRowS + ((u ^ xrS) << 4) + (uint32_t)((bc8 & 1) * 8);
                    *(uint2*)(stB + by) = make_uint2(pack2h(bq[q].x, bq[q].y),
                                                     pack2h(bq[q].z, bq[q].w));
                }
            }
            __syncthreads();
        }

        // fused combine: atomic accumulate into out
#pragma unroll
        for (int mt = 0; mt < 4; mt++) {
            int rl = wm * 64 + mt * 16 + (lane >> 2);
#pragma unroll
            for (int half_ = 0; half_ < 2; half_++) {
                int m = m0 + rl + half_ * 8;
                if (m < cnt) {
                    int tok = g_pairTok[off + m];
                    float* op = out + (size_t)tok * HID + n0 + wn * 64 + (lane & 3) * 2;
#pragma unroll
                    for (int nt = 0; nt < 8; nt++) {
                        atomicAdd(op + nt * 8 + 0, acc[mt][nt][half_ * 2 + 0]);
                        atomicAdd(op + nt * 8 + 1, acc[mt][nt][half_ * 2 + 1]);
                    }
                }
            }
        }
    }
}

// ---------------- launch ----------------
extern "C" void kernel_launch(void* const* d_in, const int* in_sizes, int n_in,
                              void* d_out, int out_size) {
    const float* x   = nullptr;
    const float* rw  = nullptr;
    const float* Wgu = nullptr;
    const float* Wd  = nullptr;
    const int*   ri  = nullptr;
    for (int i = 0; i < n_in; i++) {
        switch (in_sizes[i]) {
            case 2097152:   x   = (const float*)d_in[i]; break;
            case 32768:     rw  = (const float*)d_in[i]; break;
            case 100663296: Wgu = (const float*)d_in[i]; break;
            case 50331648:  Wd  = (const float*)d_in[i]; break;
            case 4096:      ri  = (const int*)d_in[i];   break;
            default: break;
        }
    }
    float* out = (float*)d_out;

    cudaFuncSetAttribute(k_moe, cudaFuncAttributeMaxDynamicSharedMemorySize, SMMAX);

    k_route<<<1, NT>>>(ri, rw);
    k_zero<<<(NT * HID / 4) / 256, 256>>>((float4*)out);
    k_prep<<<(NT * HID / 4) / 256, 256>>>((const float4*)x);  // 3rd launch: ncu captures k_moe
    k_moe<<<G1TILES + G2TILES, 256, SMMAX>>>(Wgu, Wd, out);
}